// round 6
// baseline (speedup 1.0000x reference)
#include <cuda_runtime.h>
#include <cstdint>

#define S   512
#define DH  128   // STATE_DIM == HIDDEN
#define NH  16
#define MI  4     // i rows per CTA
#define MJ  16    // j cols per CTA
#define MT  64    // MI*MJ pairs per CTA
#define KC  16    // K-chunk

// scratch for precomputed hi / hj (B=2 max)
__device__ float g_hi[2 * S * DH];
__device__ float g_hj[2 * S * DH];

// ---------------------------------------------------------------------------
// Kernel 1: hi[b,s,:] = x[b,s,:] @ W1[:128] + b1 ;  hj = x @ W1[128:]
// ---------------------------------------------------------------------------
__global__ void precompute_kernel(const float* __restrict__ x,
                                  const float* __restrict__ W1,
                                  const float* __restrict__ b1) {
    __shared__ float xs[DH];
    const int row = blockIdx.x;       // b*S + s
    const int t   = threadIdx.x;      // hidden index 0..127
    xs[t] = x[row * DH + t];
    __syncthreads();
    float ai = b1[t];
    float aj = 0.f;
#pragma unroll 8
    for (int d = 0; d < DH; ++d) {
        const float xv = xs[d];
        ai = fmaf(xv, W1[d * DH + t], ai);
        aj = fmaf(xv, W1[(DH + d) * DH + t], aj);
    }
    g_hi[row * DH + t] = ai;
    g_hj[row * DH + t] = aj;
}

// ---------------------------------------------------------------------------
// Kernel 2: per-tile pairwise MLP
// ---------------------------------------------------------------------------
struct SmemMain {
    float hi[MI][DH];          // 2 KB
    float hj[MJ][DH];          // 8 KB
    float As[KC][MT + 4];      // relu(hi+hj) chunk, [k][m], padded
    float Bs[KC][DH];          // W2 chunk, [k][n]
};
struct SmemEpi {
    float h2[MT][DH + 1];      // 129-stride: conflict-free column reads
    float w3[DH * NH];
};
union SmemU { SmemMain m; SmemEpi e; };

__global__ __launch_bounds__(256)
void main_kernel(const float* __restrict__ W2,
                 const float* __restrict__ b2,
                 const float* __restrict__ W3,
                 const float* __restrict__ b3,
                 const float* __restrict__ temps,
                 const uint32_t* __restrict__ mask,   // bool -> int32/float32 word; !=0 test
                 float* __restrict__ out) {
    __shared__ SmemU sm;

    const int bid = blockIdx.x;
    const int b   = bid >> 12;           // 4096 tiles per batch
    const int rem = bid & 4095;
    const int i0  = (rem >> 5) * MI;     // 128 i-tiles
    const int j0  = (rem & 31) * MJ;     // 32  j-tiles

    const int tid = threadIdx.x;
    const int tx  = tid & 15;            // n-dim owner: n = tx*8 .. +7
    const int ty  = tid >> 4;            // m-dim owner: m = ty*4 .. +3

    // preload hi / hj tiles (contiguous rows)
    {
        const float* srci = &g_hi[((size_t)b * S + i0) * DH];
        for (int idx = tid; idx < MI * DH; idx += 256)
            (&sm.m.hi[0][0])[idx] = srci[idx];
        const float* srcj = &g_hj[((size_t)b * S + j0) * DH];
        for (int idx = tid; idx < MJ * DH; idx += 256)
            (&sm.m.hj[0][0])[idx] = srcj[idx];
    }

    float acc[4][8];
#pragma unroll
    for (int mm = 0; mm < 4; ++mm)
#pragma unroll
        for (int nn = 0; nn < 8; ++nn) acc[mm][nn] = 0.f;

    for (int kc = 0; kc < DH / KC; ++kc) {
        __syncthreads();
        // stage As: relu(hi+hj); staging role: k = ty, m = tx*4+mm
        {
            const int kg = kc * KC + ty;
#pragma unroll
            for (int mm = 0; mm < 4; ++mm) {
                const int m  = tx * 4 + mm;
                const int il = m >> 4, jl = m & 15;
                sm.m.As[ty][m] = fmaxf(sm.m.hi[il][kg] + sm.m.hj[jl][kg], 0.f);
            }
        }
        // stage Bs: W2[kc*16 .. +16)[0..128), float4-coalesced
#pragma unroll
        for (int t4 = 0; t4 < 2; ++t4) {
            const int idx4 = tid + t4 * 256;          // 0..511
            const int k    = idx4 >> 5;
            const int n4   = idx4 & 31;
            const float4 w = *(const float4*)&W2[(size_t)(kc * KC + k) * DH + n4 * 4];
            *(float4*)&sm.m.Bs[k][n4 * 4] = w;
        }
        __syncthreads();

#pragma unroll
        for (int kk = 0; kk < KC; ++kk) {
            const float4 av = *(const float4*)&sm.m.As[kk][ty * 4];
            const float4 b0 = *(const float4*)&sm.m.Bs[kk][tx * 8];
            const float4 b1v = *(const float4*)&sm.m.Bs[kk][tx * 8 + 4];
            const float a[4] = {av.x, av.y, av.z, av.w};
            const float bb[8] = {b0.x, b0.y, b0.z, b0.w, b1v.x, b1v.y, b1v.z, b1v.w};
#pragma unroll
            for (int mm = 0; mm < 4; ++mm)
#pragma unroll
                for (int nn = 0; nn < 8; ++nn)
                    acc[mm][nn] = fmaf(a[mm], bb[nn], acc[mm][nn]);
        }
    }

    // ---- epilogue: h2 = relu(acc + b2) -> smem; comp = h2 @ W3 + b3 ----
    __syncthreads();                       // main-loop smem reads complete
    float b2v[8];
#pragma unroll
    for (int nn = 0; nn < 8; ++nn) b2v[nn] = __ldg(&b2[tx * 8 + nn]);
#pragma unroll
    for (int mm = 0; mm < 4; ++mm)
#pragma unroll
        for (int nn = 0; nn < 8; ++nn)
            sm.e.h2[ty * 4 + mm][tx * 8 + nn] = fmaxf(acc[mm][nn] + b2v[nn], 0.f);

    for (int idx = tid; idx < DH * NH; idx += 256)
        sm.e.w3[idx] = W3[idx];
    __syncthreads();

    const int m   = tid & 63;              // pair index within tile
    const int nh0 = (tid >> 6) << 2;       // 4 heads per thread
    float c0 = __ldg(&b3[nh0 + 0]);
    float c1 = __ldg(&b3[nh0 + 1]);
    float c2 = __ldg(&b3[nh0 + 2]);
    float c3 = __ldg(&b3[nh0 + 3]);
#pragma unroll 4
    for (int k = 0; k < DH; ++k) {
        const float  hv = sm.e.h2[m][k];
        const float4 wv = *(const float4*)&sm.e.w3[k * NH + nh0];
        c0 = fmaf(hv, wv.x, c0);
        c1 = fmaf(hv, wv.y, c1);
        c2 = fmaf(hv, wv.z, c2);
        c3 = fmaf(hv, wv.w, c3);
    }

    const int i = i0 + (m >> 4);
    const int j = j0 + (m & 15);
    // mask was a numpy bool -> harness stores as a 32-bit dtype (int32 or
    // float32). In both, "true" is a nonzero 32-bit word and "false" is 0.
    const bool mk = mask[((size_t)b * S + i) * S + j] != 0u;
    const float ninf = __int_as_float(0xff800000);
    float c[4] = {c0, c1, c2, c3};
#pragma unroll
    for (int q = 0; q < 4; ++q) {
        const int nh = nh0 + q;
        float v = c[q] * __ldg(&temps[nh]);
        out[(((size_t)b * NH + nh) * S + i) * S + j] = mk ? v : ninf;
    }
}

// ---------------------------------------------------------------------------
extern "C" void kernel_launch(void* const* d_in, const int* in_sizes, int n_in,
                              void* d_out, int out_size) {
    const float*    x     = (const float*)d_in[0];
    const uint32_t* mask  = (const uint32_t*)d_in[1];
    const float*    W1    = (const float*)d_in[2];
    const float*    b1    = (const float*)d_in[3];
    const float*    W2    = (const float*)d_in[4];
    const float*    b2    = (const float*)d_in[5];
    const float*    W3    = (const float*)d_in[6];
    const float*    b3    = (const float*)d_in[7];
    const float*    temps = (const float*)d_in[8];

    const int B = in_sizes[0] / (S * DH);   // = 2

    precompute_kernel<<<B * S, DH>>>(x, W1, b1);
    main_kernel<<<B * 4096, 256>>>(W2, b2, W3, b3, temps, mask, (float*)d_out);
}

// round 8
// speedup vs baseline: 2.9714x; 2.9714x over previous
#include <cuda_runtime.h>
#include <cuda_bf16.h>
#include <cstdint>

#define S   512
#define DH  128
#define NH  16

// scratch for precomputed hi / hj (B=2)
__device__ float g_hi[2 * S * DH];
__device__ float g_hj[2 * S * DH];

// ---------------------------------------------------------------------------
// helpers
// ---------------------------------------------------------------------------
__device__ __forceinline__ uint32_t smem_u32(const void* p) {
    uint32_t a;
    asm("{ .reg .u64 t; cvta.to.shared.u64 t, %1; cvt.u32.u64 %0, t; }"
        : "=r"(a) : "l"(p));
    return a;
}

__device__ __forceinline__ void ldsm4(uint32_t* r, uint32_t addr) {
    asm volatile("ldmatrix.sync.aligned.m8n8.x4.shared.b16 {%0,%1,%2,%3}, [%4];"
                 : "=r"(r[0]), "=r"(r[1]), "=r"(r[2]), "=r"(r[3]) : "r"(addr));
}

__device__ __forceinline__ void mma16816(float* c, const uint32_t* a,
                                         uint32_t b0, uint32_t b1) {
    asm volatile(
        "mma.sync.aligned.m16n8k16.row.col.f32.bf16.bf16.f32 "
        "{%0,%1,%2,%3}, {%4,%5,%6,%7}, {%8,%9}, {%0,%1,%2,%3};"
        : "+f"(c[0]), "+f"(c[1]), "+f"(c[2]), "+f"(c[3])
        : "r"(a[0]), "r"(a[1]), "r"(a[2]), "r"(a[3]), "r"(b0), "r"(b1));
}

__device__ __forceinline__ void bsplit(float v, unsigned short& h, unsigned short& l) {
    __nv_bfloat16 bh = __float2bfloat16_rn(v);
    float r = v - __bfloat162float(bh);
    h = __bfloat16_as_ushort(bh);
    l = __bfloat16_as_ushort(__float2bfloat16_rn(r));
}
__device__ __forceinline__ uint32_t pack2(float v0, float v1, uint32_t& lo) {
    unsigned short h0, l0, h1, l1;
    bsplit(v0, h0, l0); bsplit(v1, h1, l1);
    lo = (uint32_t)l0 | ((uint32_t)l1 << 16);
    return (uint32_t)h0 | ((uint32_t)h1 << 16);
}

// ---------------------------------------------------------------------------
// smem layout (bytes). bf16 matrices use row stride 136 elems = 272 B
// (272/4 = 68 ≡ 4 mod 32 -> ldmatrix conflict-free).
// ---------------------------------------------------------------------------
#define SA   136      // bf16 row stride (elems)
#define SAB  272      // bytes
#define SJF  129      // hj fp32 row stride (conflict-free reads)

#define HI_OFF   0        // 8  * 128 f32  (4096)
#define HJ_OFF   4096     // 16 * 129 f32  (8256 -> pad 8320)
#define B2_OFF   12416    // 128 f32
#define B3_OFF   12928    // 16 f32
#define TP_OFF   12992    // 16 f32
#define W2H_OFF  13056    // 128*136 bf16 (34816)
#define W2L_OFF  47872
#define W3H_OFF  82688    // 16*136 bf16 (4352)
#define W3L_OFF  87040
#define AH_OFF   91392    // 128*136 bf16 (A / h2 hi)
#define AL_OFF   126208
#define SMEM_TOTAL 161024

// ---------------------------------------------------------------------------
// Kernel 1: hi = x @ W1[:128] + b1 ;  hj = x @ W1[128:]
// ---------------------------------------------------------------------------
__global__ void precompute_kernel(const float* __restrict__ x,
                                  const float* __restrict__ W1,
                                  const float* __restrict__ b1) {
    __shared__ float xs[DH];
    const int row = blockIdx.x;
    const int t   = threadIdx.x;
    xs[t] = x[row * DH + t];
    __syncthreads();
    float ai = b1[t];
    float aj = 0.f;
#pragma unroll 8
    for (int d = 0; d < DH; ++d) {
        const float xv = xs[d];
        ai = fmaf(xv, W1[d * DH + t], ai);
        aj = fmaf(xv, W1[(DH + d) * DH + t], aj);
    }
    g_hi[row * DH + t] = ai;
    g_hj[row * DH + t] = aj;
}

// ---------------------------------------------------------------------------
// Kernel 2: persistent mma.sync pairwise-MLP. 256 thr = 8 warps.
// Tile = 128 pairs (8 i x 16 j). Layer2: M128 N128 K128; Layer3: N16.
// Warp grid layer2: 4 (M) x 2 (N): warp tile M32 x N64.
// ---------------------------------------------------------------------------
__global__ __launch_bounds__(256, 1)
void main_kernel(const float* __restrict__ W2, const float* __restrict__ b2,
                 const float* __restrict__ W3, const float* __restrict__ b3,
                 const float* __restrict__ temps, const uint32_t* __restrict__ mask,
                 float* __restrict__ out, int ntiles) {
    extern __shared__ __align__(1024) char smc[];
    const uint32_t smu = smem_u32(smc);
    const int tid = threadIdx.x;
    const int wid = tid >> 5;
    const int lid = tid & 31;

    // ---- one-time staging ----
    for (int idx = tid; idx < DH * DH; idx += 256) {       // W2[k][n] -> [n][k]
        const int k = idx >> 7, n = idx & 127;
        unsigned short h, l; bsplit(W2[idx], h, l);
        const uint32_t off = (uint32_t)(n * SAB + k * 2);
        *(unsigned short*)(smc + W2H_OFF + off) = h;
        *(unsigned short*)(smc + W2L_OFF + off) = l;
    }
    for (int idx = tid; idx < DH * NH; idx += 256) {       // W3[k][c] -> [c][k]
        const int k = idx >> 4, c = idx & 15;
        unsigned short h, l; bsplit(W3[idx], h, l);
        const uint32_t off = (uint32_t)(c * SAB + k * 2);
        *(unsigned short*)(smc + W3H_OFF + off) = h;
        *(unsigned short*)(smc + W3L_OFF + off) = l;
    }
    if (tid < DH) ((float*)(smc + B2_OFF))[tid] = b2[tid];
    if (tid < NH) {
        ((float*)(smc + B3_OFF))[tid] = b3[tid];
        ((float*)(smc + TP_OFF))[tid] = temps[tid];
    }

    const float* b2s = (const float*)(smc + B2_OFF);
    const float* b3s = (const float*)(smc + B3_OFF);
    const float* tps = (const float*)(smc + TP_OFF);

    // per-lane ldmatrix address pattern: row = row0 + (lid&15), colbyte = ((lid>>4)<<3)*2
    const uint32_t lrow  = (uint32_t)(lid & 15);
    const uint32_t lcolb = (uint32_t)(((lid >> 4) << 3) << 1);

    // layer-2 warp tiling
    const int wm = wid & 3;            // 0..3 -> m_base
    const int wn = wid >> 2;           // 0..1 -> n_base
    const int m_base = wm * 32;
    const int n_base = wn * 64;

    uint32_t aoffH[2], aoffL[2], boffH[4], boffL[4];
#pragma unroll
    for (int mt = 0; mt < 2; ++mt) {
        const uint32_t off = (uint32_t)(m_base + mt * 16 + lrow) * SAB + lcolb;
        aoffH[mt] = smu + AH_OFF + off;
        aoffL[mt] = smu + AL_OFF + off;
    }
#pragma unroll
    for (int np = 0; np < 4; ++np) {
        const uint32_t off = (uint32_t)(n_base + np * 16 + lrow) * SAB + lcolb;
        boffH[np] = smu + W2H_OFF + off;
        boffL[np] = smu + W2L_OFF + off;
    }
    // layer-3 addresses: warp wid covers rows m0 = wid*16
    const uint32_t a3off = (uint32_t)(wid * 16 + lrow) * SAB + lcolb;
    const uint32_t b3offH = smu + W3H_OFF + lrow * SAB + lcolb;
    const uint32_t b3offL = smu + W3L_OFF + lrow * SAB + lcolb;

    const int qr = lid >> 2;           // 0..7
    const int qc = (lid & 3) << 1;     // 0,2,4,6

    for (int t = blockIdx.x; t < ntiles; t += gridDim.x) {
        const int b  = t >> 11;            // 2048 tiles per batch
        const int r  = t & 2047;
        const int i0 = (r >> 5) << 3;      // 64 i-tiles * 8
        const int j0 = (r & 31) << 4;      // 32 j-tiles * 16

        // ---- stage hi / hj ----
        {
            const float* src = g_hi + ((size_t)(b * S + i0)) * DH;
            for (int idx = tid; idx < 8 * DH; idx += 256)
                ((float*)(smc + HI_OFF))[idx] = src[idx];
            src = g_hj + ((size_t)(b * S + j0)) * DH;
            for (int idx = tid; idx < 16 * DH; idx += 256)
                ((float*)(smc + HJ_OFF))[(idx >> 7) * SJF + (idx & 127)] = src[idx];
        }
        __syncthreads();

        // ---- build A = relu(hi+hj) -> bf16 hi/lo ----
        {
            const int m     = tid >> 1;              // pair row 0..127
            const int khalf = (tid & 1) << 6;        // 0 or 64
            const float* hip = (const float*)(smc + HI_OFF) + (m >> 4) * DH + khalf;
            const float* hjp = (const float*)(smc + HJ_OFF) + (m & 15) * SJF + khalf;
            const uint32_t wbase = (uint32_t)m * SAB + (uint32_t)khalf * 2;
#pragma unroll
            for (int kk = 0; kk < 64; kk += 2) {
                const float v0 = fmaxf(hip[kk]     + hjp[kk],     0.f);
                const float v1 = fmaxf(hip[kk + 1] + hjp[kk + 1], 0.f);
                uint32_t lo;
                const uint32_t hi = pack2(v0, v1, lo);
                *(uint32_t*)(smc + AH_OFF + wbase + kk * 2) = hi;
                *(uint32_t*)(smc + AL_OFF + wbase + kk * 2) = lo;
            }
        }
        __syncthreads();

        // ---- layer-2 GEMM: acc = Ah*Bh + Ah*Bl + Al*Bh ----
        float acc[2][8][4];
#pragma unroll
        for (int mt = 0; mt < 2; ++mt)
#pragma unroll
            for (int nt = 0; nt < 8; ++nt)
#pragma unroll
                for (int e = 0; e < 4; ++e) acc[mt][nt][e] = 0.f;

#pragma unroll
        for (int k0 = 0; k0 < 128; k0 += 16) {
            const uint32_t kb = (uint32_t)k0 * 2;
            uint32_t aH[2][4], aL[2][4], bH[4][4], bL[4][4];
#pragma unroll
            for (int mt = 0; mt < 2; ++mt) {
                ldsm4(aH[mt], aoffH[mt] + kb);
                ldsm4(aL[mt], aoffL[mt] + kb);
            }
#pragma unroll
            for (int np = 0; np < 4; ++np) {
                ldsm4(bH[np], boffH[np] + kb);
                ldsm4(bL[np], boffL[np] + kb);
            }
#pragma unroll
            for (int mt = 0; mt < 2; ++mt)
#pragma unroll
                for (int nt = 0; nt < 8; ++nt) {
                    const int np = nt >> 1, sc = nt & 1;
                    mma16816(acc[mt][nt], aH[mt], bH[np][sc], bH[np][2 + sc]);
                    mma16816(acc[mt][nt], aH[mt], bL[np][sc], bL[np][2 + sc]);
                    mma16816(acc[mt][nt], aL[mt], bH[np][sc], bH[np][2 + sc]);
                }
        }
        __syncthreads();   // all Ah/Al/W2 reads done

        // ---- epilogue 1: h2 = relu(acc + b2) -> bf16 hi/lo back into A ----
#pragma unroll
        for (int mt = 0; mt < 2; ++mt)
#pragma unroll
            for (int nt = 0; nt < 8; ++nt) {
                const int n0  = n_base + nt * 8 + qc;
                const float ba = b2s[n0], bb = b2s[n0 + 1];
                const int r0 = m_base + mt * 16 + qr;
                uint32_t lo0, lo1;
                const uint32_t hi0 = pack2(fmaxf(acc[mt][nt][0] + ba, 0.f),
                                           fmaxf(acc[mt][nt][1] + bb, 0.f), lo0);
                const uint32_t hi1 = pack2(fmaxf(acc[mt][nt][2] + ba, 0.f),
                                           fmaxf(acc[mt][nt][3] + bb, 0.f), lo1);
                const uint32_t w0 = (uint32_t)r0 * SAB + (uint32_t)n0 * 2;
                *(uint32_t*)(smc + AH_OFF + w0) = hi0;
                *(uint32_t*)(smc + AL_OFF + w0) = lo0;
                const uint32_t w1 = w0 + 8u * SAB;
                *(uint32_t*)(smc + AH_OFF + w1) = hi1;
                *(uint32_t*)(smc + AL_OFF + w1) = lo1;
            }
        __syncthreads();

        // ---- layer-3 GEMM: comp = h2h*W3h + h2h*W3l + h2l*W3h (N=16) ----
        float acc2[2][4];
#pragma unroll
        for (int nt = 0; nt < 2; ++nt)
#pragma unroll
            for (int e = 0; e < 4; ++e) acc2[nt][e] = 0.f;

#pragma unroll
        for (int k0 = 0; k0 < 128; k0 += 16) {
            const uint32_t kb = (uint32_t)k0 * 2;
            uint32_t ah[4], al[4], bh[4], bl[4];
            ldsm4(ah, smu + AH_OFF + a3off + kb);
            ldsm4(al, smu + AL_OFF + a3off + kb);
            ldsm4(bh, b3offH + kb);
            ldsm4(bl, b3offL + kb);
#pragma unroll
            for (int nt = 0; nt < 2; ++nt) {
                mma16816(acc2[nt], ah, bh[nt], bh[2 + nt]);
                mma16816(acc2[nt], ah, bl[nt], bl[2 + nt]);
                mma16816(acc2[nt], al, bh[nt], bh[2 + nt]);
            }
        }

        // ---- epilogue 2: scale, mask, store ----
        {
            const float ninf = __int_as_float(0xff800000);
            const size_t bb = (size_t)b * NH * S * S;
#pragma unroll
            for (int e = 0; e < 2; ++e) {
                const int m = wid * 16 + qr + e * 8;
                const int i = i0 + (m >> 4);
                const int j = j0 + (m & 15);
                const bool mk = mask[((size_t)b * S + i) * S + j] != 0u;
                const size_t obase = bb + (size_t)i * S + j;
#pragma unroll
                for (int nt = 0; nt < 2; ++nt) {
                    const int c0 = nt * 8 + qc;
                    const float v0 = (acc2[nt][e * 2 + 0] + b3s[c0]) * tps[c0];
                    const float v1 = (acc2[nt][e * 2 + 1] + b3s[c0 + 1]) * tps[c0 + 1];
                    out[obase + (size_t)c0 * S * S]       = mk ? v0 : ninf;
                    out[obase + (size_t)(c0 + 1) * S * S] = mk ? v1 : ninf;
                }
            }
        }
        // next iteration's stage + its __syncthreads separates layer-3 smem
        // reads from the next build's Ah/Al writes.
    }
}

// ---------------------------------------------------------------------------
extern "C" void kernel_launch(void* const* d_in, const int* in_sizes, int n_in,
                              void* d_out, int out_size) {
    const float*    x     = (const float*)d_in[0];
    const uint32_t* mask  = (const uint32_t*)d_in[1];
    const float*    W1    = (const float*)d_in[2];
    const float*    b1    = (const float*)d_in[3];
    const float*    W2    = (const float*)d_in[4];
    const float*    b2    = (const float*)d_in[5];
    const float*    W3    = (const float*)d_in[6];
    const float*    b3    = (const float*)d_in[7];
    const float*    temps = (const float*)d_in[8];

    const int B = in_sizes[0] / (S * DH);   // = 2
    const int ntiles = B * 2048;            // 128-pair tiles

    cudaFuncSetAttribute(main_kernel, cudaFuncAttributeMaxDynamicSharedMemorySize,
                         SMEM_TOTAL);

    precompute_kernel<<<B * S, DH>>>(x, W1, b1);
    main_kernel<<<152, 256, SMEM_TOTAL>>>(W2, b2, W3, b3, temps, mask,
                                          (float*)d_out, ntiles);
}